// round 7
// baseline (speedup 1.0000x reference)
#include <cuda_runtime.h>
#include <stdint.h>

#define N_NODES 50000
#define N_EDGES 600000
#define IN_DIM 128
#define HID 256
#define N_CLASSES 16

// ---------------- device scratch (no allocation allowed) ----------------
__device__ int   g_src[N_EDGES];
__device__ int   g_dst[N_EDGES];
__device__ float g_deg[N_NODES];
__device__ float g_invdeg[N_NODES];
__device__ float g_agg[(size_t)N_NODES * HID];   // layer1 uses stride 128, layer2 stride 256
__device__ float g_h1[(size_t)N_NODES * HID];
__device__ float g_h2[(size_t)N_NODES * HID];

// ---------------- helpers ----------------
__device__ __forceinline__ void red_add4(float* addr, float4 v) {
    atomicAdd(addr + 0, v.x);
    atomicAdd(addr + 1, v.y);
    atomicAdd(addr + 2, v.z);
    atomicAdd(addr + 3, v.w);
}

// ---------------- edge canonicalization: int32, (2,E) split [src row | dst row] ----------------
__global__ void convert_edges(const int* __restrict__ ei) {
    int e = blockIdx.x * blockDim.x + threadIdx.x;
    if (e >= N_EDGES) return;
    int s = ei[e];
    int d = ei[N_EDGES + e];
    g_src[e] = min(max(s, 0), N_NODES - 1);
    g_dst[e] = min(max(d, 0), N_NODES - 1);
}

// ---------------- zero scratch ----------------
__global__ void zero_agg_deg(int n, int do_deg) {
    int i = blockIdx.x * blockDim.x + threadIdx.x;
    if (i < n) g_agg[i] = 0.0f;
    if (do_deg && i < N_NODES) g_deg[i] = 0.0f;
}

// ---------------- scatter layer 1: agg[dst] += x[src], deg[dst] += 1 ----------------
__global__ void scatter1(const float* __restrict__ x) {
    int idx = blockIdx.x * blockDim.x + threadIdx.x;
    int e = idx >> 5;
    int lane = idx & 31;
    if (e >= N_EDGES) return;
    int s = g_src[e];
    int d = g_dst[e];
    const float4* xr = reinterpret_cast<const float4*>(x + (size_t)s * IN_DIM);
    float4 v = xr[lane];
    red_add4(g_agg + (size_t)d * IN_DIM + lane * 4, v);
    if (lane == 0) atomicAdd(&g_deg[d], 1.0f);
}

// ---------------- scatter layer 2: agg[dst] += h1[src] (256 floats) ----------------
__global__ void scatter2() {
    int idx = blockIdx.x * blockDim.x + threadIdx.x;
    int e = idx >> 5;
    int lane = idx & 31;
    if (e >= N_EDGES) return;
    int s = g_src[e];
    int d = g_dst[e];
    const float4* hr = reinterpret_cast<const float4*>(g_h1 + (size_t)s * HID);
    float4 v0 = hr[lane];
    float4 v1 = hr[lane + 32];
    float* base = g_agg + (size_t)d * HID;
    red_add4(base + lane * 4, v0);
    red_add4(base + (lane + 32) * 4, v1);
}

// ---------------- inv degree ----------------
__global__ void make_invdeg() {
    int i = blockIdx.x * blockDim.x + threadIdx.x;
    if (i < N_NODES) g_invdeg[i] = 1.0f / fmaxf(g_deg[i], 1.0f);
}

// ---------------- fused SAGE GEMM ----------------
// C = relu( (g_agg*invdeg) @ W1 + A2 @ W2 + bias ),  virtual K = 2*KHALF
template <int KHALF, bool RELU, int OUTBUF>   // OUTBUF: 1 -> g_h1, 2 -> g_h2
__global__ void sage_gemm(const float* __restrict__ A2,
                          const float* __restrict__ W1,
                          const float* __restrict__ W2,
                          const float* __restrict__ bias) {
    __shared__ float As[64][17];
    __shared__ float Bs[16][64];

    const int tid = threadIdx.x;
    const int tx = tid & 15;
    const int ty = tid >> 4;
    const int rowBase = blockIdx.x * 64;
    const int colBase = blockIdx.y * 64;

    float acc[4][4];
#pragma unroll
    for (int i = 0; i < 4; i++)
#pragma unroll
        for (int j = 0; j < 4; j++) acc[i][j] = 0.0f;

    const int KTOT = 2 * KHALF;
    for (int k0 = 0; k0 < KTOT; k0 += 16) {
#pragma unroll
        for (int i = 0; i < 4; i++) {
            int idx = tid + 256 * i;
            int r = idx >> 4;
            int kk = idx & 15;
            int row = rowBase + r;
            int gk = k0 + kk;
            float val = 0.0f;
            if (row < N_NODES) {
                if (gk < KHALF) val = g_agg[(size_t)row * KHALF + gk] * g_invdeg[row];
                else            val = A2[(size_t)row * KHALF + (gk - KHALF)];
            }
            As[r][kk] = val;
        }
#pragma unroll
        for (int i = 0; i < 4; i++) {
            int idx = tid + 256 * i;
            int kk = idx >> 6;
            int col = idx & 63;
            int gk = k0 + kk;
            float val;
            if (gk < KHALF) val = W1[(size_t)gk * HID + colBase + col];
            else            val = W2[(size_t)(gk - KHALF) * HID + colBase + col];
            Bs[kk][col] = val;
        }
        __syncthreads();

#pragma unroll
        for (int kk = 0; kk < 16; kk++) {
            float a0 = As[ty * 4 + 0][kk];
            float a1 = As[ty * 4 + 1][kk];
            float a2 = As[ty * 4 + 2][kk];
            float a3 = As[ty * 4 + 3][kk];
            float4 b = *reinterpret_cast<const float4*>(&Bs[kk][tx * 4]);
            acc[0][0] += a0 * b.x; acc[0][1] += a0 * b.y; acc[0][2] += a0 * b.z; acc[0][3] += a0 * b.w;
            acc[1][0] += a1 * b.x; acc[1][1] += a1 * b.y; acc[1][2] += a1 * b.z; acc[1][3] += a1 * b.w;
            acc[2][0] += a2 * b.x; acc[2][1] += a2 * b.y; acc[2][2] += a2 * b.z; acc[2][3] += a2 * b.w;
            acc[3][0] += a3 * b.x; acc[3][1] += a3 * b.y; acc[3][2] += a3 * b.z; acc[3][3] += a3 * b.w;
        }
        __syncthreads();
    }

    float* C = (OUTBUF == 1) ? g_h1 : g_h2;   // device symbol resolved IN KERNEL (correct)
    int col = colBase + tx * 4;
    float4 bi = *reinterpret_cast<const float4*>(&bias[col]);
#pragma unroll
    for (int i = 0; i < 4; i++) {
        int row = rowBase + ty * 4 + i;
        if (row >= N_NODES) break;
        float4 o;
        o.x = acc[i][0] + bi.x;
        o.y = acc[i][1] + bi.y;
        o.z = acc[i][2] + bi.z;
        o.w = acc[i][3] + bi.w;
        if (RELU) {
            o.x = fmaxf(o.x, 0.0f); o.y = fmaxf(o.y, 0.0f);
            o.z = fmaxf(o.z, 0.0f); o.w = fmaxf(o.w, 0.0f);
        }
        *reinterpret_cast<float4*>(&C[(size_t)row * HID + col]) = o;
    }
}

// ---------------- classifier: out = h2 @ wc + bc ----------------
__global__ void classifier_k(const float* __restrict__ wc,
                             const float* __restrict__ bc,
                             float* __restrict__ out) {
    __shared__ float w[HID * N_CLASSES];
    __shared__ float hrow[8][HID];
    for (int i = threadIdx.x; i < HID * N_CLASSES; i += blockDim.x)
        w[i] = wc[i];
    __syncthreads();

    int warp = threadIdx.x >> 5;
    int lane = threadIdx.x & 31;
    int row = blockIdx.x * 8 + warp;
    if (row >= N_NODES) return;

    const float* h = g_h2 + (size_t)row * HID;
    for (int k = lane; k < HID; k += 32) hrow[warp][k] = h[k];
    __syncwarp();

    int c = lane & 15;
    int p = lane >> 4;
    float acc = 0.0f;
    int kbeg = p * (HID / 2);
#pragma unroll 8
    for (int k = kbeg; k < kbeg + HID / 2; k++)
        acc += hrow[warp][k] * w[k * N_CLASSES + c];
    acc += __shfl_xor_sync(0xffffffffu, acc, 16);
    if (lane < 16) out[(size_t)row * N_CLASSES + lane] = acc + bc[lane];
}

// ---------------- launch ----------------
extern "C" void kernel_launch(void* const* d_in, const int* in_sizes, int n_in,
                              void* d_out, int out_size) {
    const float* x    = (const float*)d_in[0];
    const int*   ei   = (const int*)d_in[1];
    const float* w1_l = (const float*)d_in[2];
    const float* b1_l = (const float*)d_in[3];
    const float* w1_r = (const float*)d_in[4];
    const float* w2_l = (const float*)d_in[5];
    const float* b2_l = (const float*)d_in[6];
    const float* w2_r = (const float*)d_in[7];
    const float* wc   = (const float*)d_in[8];
    const float* bc   = (const float*)d_in[9];
    float* out = (float*)d_out;

    // CRITICAL: resolve the REAL device address of g_h1. Passing the __device__
    // symbol directly as a kernel arg passes the host shadow address; on GB300
    // (ATS/HMM) that silently dereferences zero-filled host memory.
    void* h1_dev = nullptr;
    cudaGetSymbolAddress(&h1_dev, g_h1);
    const float* h1_ptr = (const float*)h1_dev;

    // ---- edges + degree ----
    convert_edges<<<(N_EDGES + 255) / 256, 256>>>(ei);

    // ---- layer 1 ----
    {
        int n = N_NODES * IN_DIM;
        zero_agg_deg<<<(n + 255) / 256, 256>>>(n, 1);
    }
    scatter1<<<(N_EDGES * 32 + 255) / 256, 256>>>(x);
    make_invdeg<<<(N_NODES + 255) / 256, 256>>>();
    {
        dim3 grid((N_NODES + 63) / 64, HID / 64);
        sage_gemm<IN_DIM, true, 1><<<grid, 256>>>(x, w1_l, w1_r, b1_l);
    }

    // ---- layer 2 ----
    {
        int n = N_NODES * HID;
        zero_agg_deg<<<(n + 255) / 256, 256>>>(n, 0);
    }
    scatter2<<<(N_EDGES * 32 + 255) / 256, 256>>>();
    {
        dim3 grid((N_NODES + 63) / 64, HID / 64);
        sage_gemm<HID, true, 2><<<grid, 256>>>(h1_ptr, w2_l, w2_r, b2_l);
    }

    // ---- classifier ----
    classifier_k<<<(N_NODES + 7) / 8, 256>>>(wc, bc, out);
}

// round 8
// speedup vs baseline: 4.6286x; 4.6286x over previous
#include <cuda_runtime.h>
#include <stdint.h>

#define N_NODES 50000
#define N_EDGES 600000
#define IN_DIM 128
#define HID 256
#define N_CLASSES 16

// ---------------- device scratch (no allocation allowed) ----------------
__device__ int   g_cnt[N_NODES];
__device__ int   g_rowptr[N_NODES + 1];
__device__ int   g_cursor[N_NODES];
__device__ int   g_col[N_EDGES];                  // src ids bucketed by dst
__device__ float g_agg[(size_t)N_NODES * HID];    // mean (tf32-rounded); stride 128 (L1) / 256 (L2)
__device__ float g_h1[(size_t)N_NODES * HID];     // tf32-rounded activations
__device__ float g_h2[(size_t)N_NODES * HID];     // fp32
__device__ float g_xt[(size_t)N_NODES * IN_DIM];  // x in tf32
__device__ float g_w1t[2 * IN_DIM * HID];         // [w1_l ; w1_r] tf32
__device__ float g_w2t[2 * HID * HID];            // [w2_l ; w2_r] tf32

// ---------------- helpers ----------------
__device__ __forceinline__ float to_tf32(float x) {
    uint32_t u;
    asm("cvt.rna.tf32.f32 %0, %1;" : "=r"(u) : "f"(x));
    return __uint_as_float(u);
}

__device__ __forceinline__ void mma_tf32(float* d, const uint32_t* a, uint32_t b0, uint32_t b1) {
    asm volatile(
        "mma.sync.aligned.m16n8k8.row.col.f32.tf32.tf32.f32 "
        "{%0,%1,%2,%3}, {%4,%5,%6,%7}, {%8,%9}, {%0,%1,%2,%3};"
        : "+f"(d[0]), "+f"(d[1]), "+f"(d[2]), "+f"(d[3])
        : "r"(a[0]), "r"(a[1]), "r"(a[2]), "r"(a[3]), "r"(b0), "r"(b1));
}

// ---------------- CSR build ----------------
__global__ void zero_cnt() {
    int i = blockIdx.x * blockDim.x + threadIdx.x;
    if (i < N_NODES) g_cnt[i] = 0;
}
__global__ void hist_kernel(const int* __restrict__ ei) {
    int e = blockIdx.x * blockDim.x + threadIdx.x;
    if (e >= N_EDGES) return;
    int d = min(max(ei[N_EDGES + e], 0), N_NODES - 1);
    atomicAdd(&g_cnt[d], 1);
}
__global__ void scan_kernel() {
    __shared__ int sm[1024];
    __shared__ int carry;
    int tid = threadIdx.x;
    if (tid == 0) carry = 0;
    __syncthreads();
    for (int base = 0; base < N_NODES; base += 1024) {
        int v = (base + tid < N_NODES) ? g_cnt[base + tid] : 0;
        sm[tid] = v;
        __syncthreads();
        for (int off = 1; off < 1024; off <<= 1) {
            int t = (tid >= off) ? sm[tid - off] : 0;
            __syncthreads();
            sm[tid] += t;
            __syncthreads();
        }
        int excl = sm[tid] - v;
        if (base + tid < N_NODES) {
            g_rowptr[base + tid] = carry + excl;
            g_cursor[base + tid] = carry + excl;
        }
        __syncthreads();
        if (tid == 0) carry += sm[1023];
        __syncthreads();
    }
    if (tid == 0) g_rowptr[N_NODES] = carry;
}
__global__ void fill_kernel(const int* __restrict__ ei) {
    int e = blockIdx.x * blockDim.x + threadIdx.x;
    if (e >= N_EDGES) return;
    int s = min(max(ei[e], 0), N_NODES - 1);
    int d = min(max(ei[N_EDGES + e], 0), N_NODES - 1);
    int pos = atomicAdd(&g_cursor[d], 1);
    g_col[pos] = s;
}

// ---------------- tf32 conversion of inputs ----------------
__global__ void cvt_copy(float* __restrict__ dst, const float* __restrict__ src, int n) {
    int i = blockIdx.x * blockDim.x + threadIdx.x;
    if (i < n) dst[i] = to_tf32(src[i]);
}
__global__ void cvt_concat(float* __restrict__ dst, const float* __restrict__ a,
                           const float* __restrict__ b, int half_elems) {
    int i = blockIdx.x * blockDim.x + threadIdx.x;
    if (i >= 2 * half_elems) return;
    float v = (i < half_elems) ? a[i] : b[i - half_elems];
    dst[i] = to_tf32(v);
}

// ---------------- gather mean (CSR), warp per node ----------------
__global__ void gather_mean_128(const float* __restrict__ feat) {
    int w = (blockIdx.x * blockDim.x + threadIdx.x) >> 5;
    int lane = threadIdx.x & 31;
    if (w >= N_NODES) return;
    int beg = g_rowptr[w], end = g_rowptr[w + 1];
    float4 acc = make_float4(0.f, 0.f, 0.f, 0.f);
    for (int j = beg; j < end; j++) {
        int s = g_col[j];
        float4 v = __ldg(reinterpret_cast<const float4*>(feat + (size_t)s * IN_DIM) + lane);
        acc.x += v.x; acc.y += v.y; acc.z += v.z; acc.w += v.w;
    }
    float inv = 1.0f / (float)max(end - beg, 1);
    float4 o;
    o.x = to_tf32(acc.x * inv); o.y = to_tf32(acc.y * inv);
    o.z = to_tf32(acc.z * inv); o.w = to_tf32(acc.w * inv);
    reinterpret_cast<float4*>(g_agg + (size_t)w * IN_DIM)[lane] = o;
}
__global__ void gather_mean_256() {
    int w = (blockIdx.x * blockDim.x + threadIdx.x) >> 5;
    int lane = threadIdx.x & 31;
    if (w >= N_NODES) return;
    int beg = g_rowptr[w], end = g_rowptr[w + 1];
    float4 a0 = make_float4(0.f, 0.f, 0.f, 0.f), a1 = a0;
    for (int j = beg; j < end; j++) {
        int s = g_col[j];
        const float4* r = reinterpret_cast<const float4*>(g_h1 + (size_t)s * HID);
        float4 v0 = __ldg(r + lane);
        float4 v1 = __ldg(r + lane + 32);
        a0.x += v0.x; a0.y += v0.y; a0.z += v0.z; a0.w += v0.w;
        a1.x += v1.x; a1.y += v1.y; a1.z += v1.z; a1.w += v1.w;
    }
    float inv = 1.0f / (float)max(end - beg, 1);
    float4 o0, o1;
    o0.x = to_tf32(a0.x * inv); o0.y = to_tf32(a0.y * inv);
    o0.z = to_tf32(a0.z * inv); o0.w = to_tf32(a0.w * inv);
    o1.x = to_tf32(a1.x * inv); o1.y = to_tf32(a1.y * inv);
    o1.z = to_tf32(a1.z * inv); o1.w = to_tf32(a1.w * inv);
    float4* dst = reinterpret_cast<float4*>(g_agg + (size_t)w * HID);
    dst[lane] = o0;
    dst[lane + 32] = o1;
}

// ---------------- tf32 tensor-core SAGE GEMM ----------------
// C[M,256] = relu( Avirt[M, 2*KHALF] @ W[2*KHALF, 256] + bias )
// Avirt: k<KHALF -> A0 (mean), else A1 (self). BM=128 BN=128 BK=32, 8 warps (4m x 2n).
#define AS_STRIDE 36
#define BS_STRIDE 136
#define AS_BUF (128 * AS_STRIDE)
#define BS_BUF (32 * BS_STRIDE)

template <int KHALF, bool CVT>
__global__ void __launch_bounds__(256, 2)
sage_tf32(const float* __restrict__ A0, const float* __restrict__ A1,
          const float* __restrict__ W, const float* __restrict__ bias,
          float* __restrict__ C) {
    extern __shared__ float smem[];
    float* As = smem;                // 2 x 128 x 36
    float* Bs = smem + 2 * AS_BUF;   // 2 x 32 x 136

    const int tid = threadIdx.x;
    const int lane = tid & 31;
    const int wid = tid >> 5;
    const int wm = wid & 3;          // 0..3 -> 32 rows each
    const int wn = wid >> 2;         // 0..1 -> 64 cols each
    const int rowBase = blockIdx.x * 128;
    const int colBase = blockIdx.y * 128;
    const int NT = (2 * KHALF) / 32;

    float acc[2][8][4];
#pragma unroll
    for (int i = 0; i < 2; i++)
#pragma unroll
        for (int j = 0; j < 8; j++)
#pragma unroll
            for (int k = 0; k < 4; k++) acc[i][j][k] = 0.0f;

    auto issue = [&](int buf, int k0) {
        float* Asb = As + buf * AS_BUF;
        float* Bsb = Bs + buf * BS_BUF;
        const float* Abase = (k0 < KHALF) ? A0 : A1;
        int kb = (k0 < KHALF) ? k0 : (k0 - KHALF);
#pragma unroll
        for (int i = 0; i < 4; i++) {
            int idx = tid + 256 * i;
            int r = idx >> 3, kc = idx & 7;
            int row = rowBase + r;
            const float* src = Abase + (size_t)row * KHALF + kb + kc * 4;
            uint32_t dst = (uint32_t)__cvta_generic_to_shared(Asb + r * AS_STRIDE + kc * 4);
            int sz = (row < N_NODES) ? 16 : 0;
            asm volatile("cp.async.ca.shared.global [%0], [%1], 16, %2;"
                         :: "r"(dst), "l"(src), "r"(sz));
        }
#pragma unroll
        for (int i = 0; i < 4; i++) {
            int idx = tid + 256 * i;
            int k = idx >> 5, c4 = idx & 31;
            const float* src = W + (size_t)(k0 + k) * HID + colBase + c4 * 4;
            uint32_t dst = (uint32_t)__cvta_generic_to_shared(Bsb + k * BS_STRIDE + c4 * 4);
            asm volatile("cp.async.ca.shared.global [%0], [%1], 16;"
                         :: "r"(dst), "l"(src));
        }
        asm volatile("cp.async.commit_group;");
    };

    issue(0, 0);
    for (int t = 0; t < NT; t++) {
        if (t + 1 < NT) {
            issue((t + 1) & 1, (t + 1) * 32);
            asm volatile("cp.async.wait_group 1;");
        } else {
            asm volatile("cp.async.wait_group 0;");
        }
        __syncthreads();
        const float* Asb = As + (t & 1) * AS_BUF;
        const float* Bsb = Bs + (t & 1) * BS_BUF;
#pragma unroll
        for (int k8 = 0; k8 < 4; k8++) {
            int kb = k8 * 8;
            uint32_t a[2][4];
#pragma unroll
            for (int mt = 0; mt < 2; mt++) {
                int m = wm * 32 + mt * 16 + (lane >> 2);
                int k = kb + (lane & 3);
                a[mt][0] = __float_as_uint(Asb[m * AS_STRIDE + k]);
                a[mt][1] = __float_as_uint(Asb[(m + 8) * AS_STRIDE + k]);
                a[mt][2] = __float_as_uint(Asb[m * AS_STRIDE + k + 4]);
                a[mt][3] = __float_as_uint(Asb[(m + 8) * AS_STRIDE + k + 4]);
            }
#pragma unroll
            for (int nt = 0; nt < 8; nt++) {
                int n = wn * 64 + nt * 8 + (lane >> 2);
                int k = kb + (lane & 3);
                uint32_t b0 = __float_as_uint(Bsb[k * BS_STRIDE + n]);
                uint32_t b1 = __float_as_uint(Bsb[(k + 4) * BS_STRIDE + n]);
                mma_tf32(acc[0][nt], a[0], b0, b1);
                mma_tf32(acc[1][nt], a[1], b0, b1);
            }
        }
        __syncthreads();
    }

    // epilogue: bias + relu (+tf32 cvt)
#pragma unroll
    for (int mt = 0; mt < 2; mt++) {
        int r0 = rowBase + wm * 32 + mt * 16 + (lane >> 2);
#pragma unroll
        for (int nt = 0; nt < 8; nt++) {
            int c = colBase + wn * 64 + nt * 8 + (lane & 3) * 2;
            float bv0 = __ldg(bias + c);
            float bv1 = __ldg(bias + c + 1);
            float v0 = fmaxf(acc[mt][nt][0] + bv0, 0.0f);
            float v1 = fmaxf(acc[mt][nt][1] + bv1, 0.0f);
            float v2 = fmaxf(acc[mt][nt][2] + bv0, 0.0f);
            float v3 = fmaxf(acc[mt][nt][3] + bv1, 0.0f);
            if (CVT) {
                v0 = to_tf32(v0); v1 = to_tf32(v1);
                v2 = to_tf32(v2); v3 = to_tf32(v3);
            }
            if (r0 < N_NODES)
                *reinterpret_cast<float2*>(C + (size_t)r0 * HID + c) = make_float2(v0, v1);
            if (r0 + 8 < N_NODES)
                *reinterpret_cast<float2*>(C + (size_t)(r0 + 8) * HID + c) = make_float2(v2, v3);
        }
    }
}

// ---------------- classifier: out = h2 @ wc + bc ----------------
__global__ void classifier_k(const float* __restrict__ wc,
                             const float* __restrict__ bc,
                             float* __restrict__ out) {
    __shared__ float w[HID * N_CLASSES];
    __shared__ float hrow[8][HID];
    for (int i = threadIdx.x; i < HID * N_CLASSES; i += blockDim.x)
        w[i] = wc[i];
    __syncthreads();

    int warp = threadIdx.x >> 5;
    int lane = threadIdx.x & 31;
    int row = blockIdx.x * 8 + warp;
    if (row >= N_NODES) return;

    const float* h = g_h2 + (size_t)row * HID;
    for (int k = lane; k < HID; k += 32) hrow[warp][k] = h[k];
    __syncwarp();

    int c = lane & 15;
    int p = lane >> 4;
    float acc = 0.0f;
    int kbeg = p * (HID / 2);
#pragma unroll 8
    for (int k = kbeg; k < kbeg + HID / 2; k++)
        acc += hrow[warp][k] * w[k * N_CLASSES + c];
    acc += __shfl_xor_sync(0xffffffffu, acc, 16);
    if (lane < 16) out[(size_t)row * N_CLASSES + lane] = acc + bc[lane];
}

// ---------------- launch ----------------
extern "C" void kernel_launch(void* const* d_in, const int* in_sizes, int n_in,
                              void* d_out, int out_size) {
    const float* x    = (const float*)d_in[0];
    const int*   ei   = (const int*)d_in[1];
    const float* w1_l = (const float*)d_in[2];
    const float* b1_l = (const float*)d_in[3];
    const float* w1_r = (const float*)d_in[4];
    const float* w2_l = (const float*)d_in[5];
    const float* b2_l = (const float*)d_in[6];
    const float* w2_r = (const float*)d_in[7];
    const float* wc   = (const float*)d_in[8];
    const float* bc   = (const float*)d_in[9];
    float* out = (float*)d_out;

    // resolve REAL device addresses of symbols used as kernel args (GB300 ATS pitfall)
    void *p_agg, *p_h1, *p_h2, *p_xt, *p_w1t, *p_w2t;
    cudaGetSymbolAddress(&p_agg, g_agg);
    cudaGetSymbolAddress(&p_h1,  g_h1);
    cudaGetSymbolAddress(&p_h2,  g_h2);
    cudaGetSymbolAddress(&p_xt,  g_xt);
    cudaGetSymbolAddress(&p_w1t, g_w1t);
    cudaGetSymbolAddress(&p_w2t, g_w2t);

    const int SMEM = (2 * AS_BUF + 2 * BS_BUF) * 4;   // 71680 B
    cudaFuncSetAttribute(sage_tf32<IN_DIM, true>,
                         cudaFuncAttributeMaxDynamicSharedMemorySize, SMEM);
    cudaFuncSetAttribute(sage_tf32<HID, false>,
                         cudaFuncAttributeMaxDynamicSharedMemorySize, SMEM);

    // ---- CSR build (shared by both layers) ----
    zero_cnt<<<(N_NODES + 255) / 256, 256>>>();
    hist_kernel<<<(N_EDGES + 255) / 256, 256>>>(ei);
    scan_kernel<<<1, 1024>>>();
    fill_kernel<<<(N_EDGES + 255) / 256, 256>>>(ei);

    // ---- tf32 input conversions ----
    cvt_concat<<<(2 * IN_DIM * HID + 255) / 256, 256>>>((float*)p_w1t, w1_l, w1_r, IN_DIM * HID);
    cvt_concat<<<(2 * HID * HID + 255) / 256, 256>>>((float*)p_w2t, w2_l, w2_r, HID * HID);
    cvt_copy<<<(N_NODES * IN_DIM + 255) / 256, 256>>>((float*)p_xt, x, N_NODES * IN_DIM);

    // ---- layer 1 ----
    gather_mean_128<<<(N_NODES * 32 + 255) / 256, 256>>>(x);
    {
        dim3 grid((N_NODES + 127) / 128, HID / 128);
        sage_tf32<IN_DIM, true><<<grid, 256, SMEM>>>(
            (const float*)p_agg, (const float*)p_xt, (const float*)p_w1t, b1_l, (float*)p_h1);
    }

    // ---- layer 2 ----
    gather_mean_256<<<(N_NODES * 32 + 255) / 256, 256>>>();
    {
        dim3 grid((N_NODES + 127) / 128, HID / 128);
        sage_tf32<HID, false><<<grid, 256, SMEM>>>(
            (const float*)p_agg, (const float*)p_h1, (const float*)p_w2t, b2_l, (float*)p_h2);
    }

    // ---- classifier ----
    classifier_k<<<(N_NODES + 7) / 8, 256>>>(wc, bc, out);
}

// round 9
// speedup vs baseline: 5.5763x; 1.2048x over previous
#include <cuda_runtime.h>
#include <stdint.h>

#define N_NODES 50000
#define N_EDGES 600000
#define IN_DIM 128
#define HID 256
#define N_CLASSES 16

#define SCAN_BLOCK 256
#define N_SBLOCKS ((N_NODES + SCAN_BLOCK - 1) / SCAN_BLOCK)   // 196

// ---------------- device scratch (no allocation allowed) ----------------
__device__ int   g_cnt[N_NODES];
__device__ int   g_blockoff[N_SBLOCKS];
__device__ int   g_rowptr[N_NODES + 1];
__device__ int   g_cursor[N_NODES];
__device__ int   g_col[N_EDGES];                  // src ids bucketed by dst
__device__ float g_agg[(size_t)N_NODES * HID];
__device__ float g_h1[(size_t)N_NODES * HID];
__device__ float g_h2[(size_t)N_NODES * HID];
__device__ float g_xt[(size_t)N_NODES * IN_DIM];  // x in tf32
__device__ float g_w1t[2 * IN_DIM * HID];         // [w1_l ; w1_r] tf32
__device__ float g_w2t[2 * HID * HID];            // [w2_l ; w2_r] tf32

// ---------------- helpers ----------------
__device__ __forceinline__ float to_tf32(float x) {
    uint32_t u;
    asm("cvt.rna.tf32.f32 %0, %1;" : "=r"(u) : "f"(x));
    return __uint_as_float(u);
}

__device__ __forceinline__ void mma_tf32(float* d, const uint32_t* a, uint32_t b0, uint32_t b1) {
    asm volatile(
        "mma.sync.aligned.m16n8k8.row.col.f32.tf32.tf32.f32 "
        "{%0,%1,%2,%3}, {%4,%5,%6,%7}, {%8,%9}, {%0,%1,%2,%3};"
        : "+f"(d[0]), "+f"(d[1]), "+f"(d[2]), "+f"(d[3])
        : "r"(a[0]), "r"(a[1]), "r"(a[2]), "r"(a[3]), "r"(b0), "r"(b1));
}

__device__ __forceinline__ void f4add(float4& a, const float4 b) {
    a.x += b.x; a.y += b.y; a.z += b.z; a.w += b.w;
}

// ---------------- CSR build ----------------
__global__ void zero_cnt() {
    int i = blockIdx.x * blockDim.x + threadIdx.x;
    if (i < N_NODES) g_cnt[i] = 0;
}
__global__ void hist_kernel(const int* __restrict__ ei) {
    int e = blockIdx.x * blockDim.x + threadIdx.x;
    if (e >= N_EDGES) return;
    int d = min(max(ei[N_EDGES + e], 0), N_NODES - 1);
    atomicAdd(&g_cnt[d], 1);
}
// hierarchical scan: (1) per-block reduce, (2) scan block sums, (3) per-block scan + offset
__global__ void block_reduce_k() {
    __shared__ int sm[SCAN_BLOCK];
    int i = blockIdx.x * SCAN_BLOCK + threadIdx.x;
    sm[threadIdx.x] = (i < N_NODES) ? g_cnt[i] : 0;
    __syncthreads();
#pragma unroll
    for (int o = SCAN_BLOCK / 2; o > 0; o >>= 1) {
        if (threadIdx.x < o) sm[threadIdx.x] += sm[threadIdx.x + o];
        __syncthreads();
    }
    if (threadIdx.x == 0) g_blockoff[blockIdx.x] = sm[0];   // temp: block sum
}
__global__ void scan_blocksums_k() {
    __shared__ int sm[256];
    int t = threadIdx.x;
    int v = (t < N_SBLOCKS) ? g_blockoff[t] : 0;
    sm[t] = v;
    __syncthreads();
#pragma unroll
    for (int o = 1; o < 256; o <<= 1) {
        int u = (t >= o) ? sm[t - o] : 0;
        __syncthreads();
        sm[t] += u;
        __syncthreads();
    }
    if (t < N_SBLOCKS) g_blockoff[t] = sm[t] - v;   // exclusive block offset
}
__global__ void block_scan_k() {
    __shared__ int sm[SCAN_BLOCK];
    int i = blockIdx.x * SCAN_BLOCK + threadIdx.x;
    int v = (i < N_NODES) ? g_cnt[i] : 0;
    sm[threadIdx.x] = v;
    __syncthreads();
#pragma unroll
    for (int o = 1; o < SCAN_BLOCK; o <<= 1) {
        int u = (threadIdx.x >= o) ? sm[threadIdx.x - o] : 0;
        __syncthreads();
        sm[threadIdx.x] += u;
        __syncthreads();
    }
    if (i < N_NODES) {
        int excl = sm[threadIdx.x] - v + g_blockoff[blockIdx.x];
        g_rowptr[i] = excl;
        g_cursor[i] = excl;
    }
    if (i == 0) g_rowptr[N_NODES] = N_EDGES;
}
__global__ void fill_kernel(const int* __restrict__ ei) {
    int e = blockIdx.x * blockDim.x + threadIdx.x;
    if (e >= N_EDGES) return;
    int s = min(max(ei[e], 0), N_NODES - 1);
    int d = min(max(ei[N_EDGES + e], 0), N_NODES - 1);
    int pos = atomicAdd(&g_cursor[d], 1);
    g_col[pos] = s;
}

// ---------------- tf32 conversion of inputs ----------------
__global__ void cvt_copy(float* __restrict__ dst, const float* __restrict__ src, int n) {
    int i = blockIdx.x * blockDim.x + threadIdx.x;
    if (i < n) dst[i] = to_tf32(src[i]);
}
__global__ void cvt_concat(float* __restrict__ dst, const float* __restrict__ a,
                           const float* __restrict__ b, int half_elems) {
    int i = blockIdx.x * blockDim.x + threadIdx.x;
    if (i >= 2 * half_elems) return;
    float v = (i < half_elems) ? a[i] : b[i - half_elems];
    dst[i] = to_tf32(v);
}

// ---------------- gather mean (CSR), warp per node, 4-edge unroll for MLP ----------------
__global__ void gather_mean_128(const float* __restrict__ feat) {
    int w = (blockIdx.x * blockDim.x + threadIdx.x) >> 5;
    int lane = threadIdx.x & 31;
    if (w >= N_NODES) return;
    int beg = g_rowptr[w], end = g_rowptr[w + 1];
    float4 acc = make_float4(0.f, 0.f, 0.f, 0.f);
    int j = beg;
    for (; j + 4 <= end; j += 4) {
        int s0 = __ldg(&g_col[j + 0]);
        int s1 = __ldg(&g_col[j + 1]);
        int s2 = __ldg(&g_col[j + 2]);
        int s3 = __ldg(&g_col[j + 3]);
        float4 v0 = __ldg(reinterpret_cast<const float4*>(feat + (size_t)s0 * IN_DIM) + lane);
        float4 v1 = __ldg(reinterpret_cast<const float4*>(feat + (size_t)s1 * IN_DIM) + lane);
        float4 v2 = __ldg(reinterpret_cast<const float4*>(feat + (size_t)s2 * IN_DIM) + lane);
        float4 v3 = __ldg(reinterpret_cast<const float4*>(feat + (size_t)s3 * IN_DIM) + lane);
        f4add(acc, v0); f4add(acc, v1); f4add(acc, v2); f4add(acc, v3);
    }
    for (; j < end; j++) {
        int s = __ldg(&g_col[j]);
        float4 v = __ldg(reinterpret_cast<const float4*>(feat + (size_t)s * IN_DIM) + lane);
        f4add(acc, v);
    }
    float inv = 1.0f / (float)max(end - beg, 1);
    float4 o;
    o.x = to_tf32(acc.x * inv); o.y = to_tf32(acc.y * inv);
    o.z = to_tf32(acc.z * inv); o.w = to_tf32(acc.w * inv);
    reinterpret_cast<float4*>(g_agg + (size_t)w * IN_DIM)[lane] = o;
}
__global__ void gather_mean_256() {
    int w = (blockIdx.x * blockDim.x + threadIdx.x) >> 5;
    int lane = threadIdx.x & 31;
    if (w >= N_NODES) return;
    int beg = g_rowptr[w], end = g_rowptr[w + 1];
    float4 a0 = make_float4(0.f, 0.f, 0.f, 0.f), a1 = a0;
    int j = beg;
    for (; j + 4 <= end; j += 4) {
        int s0 = __ldg(&g_col[j + 0]);
        int s1 = __ldg(&g_col[j + 1]);
        int s2 = __ldg(&g_col[j + 2]);
        int s3 = __ldg(&g_col[j + 3]);
        const float4* r0 = reinterpret_cast<const float4*>(g_h1 + (size_t)s0 * HID);
        const float4* r1 = reinterpret_cast<const float4*>(g_h1 + (size_t)s1 * HID);
        const float4* r2 = reinterpret_cast<const float4*>(g_h1 + (size_t)s2 * HID);
        const float4* r3 = reinterpret_cast<const float4*>(g_h1 + (size_t)s3 * HID);
        float4 u0 = __ldg(r0 + lane),      u1 = __ldg(r1 + lane);
        float4 u2 = __ldg(r2 + lane),      u3 = __ldg(r3 + lane);
        float4 v0 = __ldg(r0 + lane + 32), v1 = __ldg(r1 + lane + 32);
        float4 v2 = __ldg(r2 + lane + 32), v3 = __ldg(r3 + lane + 32);
        f4add(a0, u0); f4add(a0, u1); f4add(a0, u2); f4add(a0, u3);
        f4add(a1, v0); f4add(a1, v1); f4add(a1, v2); f4add(a1, v3);
    }
    for (; j < end; j++) {
        int s = __ldg(&g_col[j]);
        const float4* r = reinterpret_cast<const float4*>(g_h1 + (size_t)s * HID);
        f4add(a0, __ldg(r + lane));
        f4add(a1, __ldg(r + lane + 32));
    }
    float inv = 1.0f / (float)max(end - beg, 1);
    float4 o0, o1;
    o0.x = to_tf32(a0.x * inv); o0.y = to_tf32(a0.y * inv);
    o0.z = to_tf32(a0.z * inv); o0.w = to_tf32(a0.w * inv);
    o1.x = to_tf32(a1.x * inv); o1.y = to_tf32(a1.y * inv);
    o1.z = to_tf32(a1.z * inv); o1.w = to_tf32(a1.w * inv);
    float4* dst = reinterpret_cast<float4*>(g_agg + (size_t)w * HID);
    dst[lane] = o0;
    dst[lane + 32] = o1;
}

// ---------------- tf32 tensor-core SAGE GEMM (as round 8) ----------------
#define AS_STRIDE 36
#define BS_STRIDE 136
#define AS_BUF (128 * AS_STRIDE)
#define BS_BUF (32 * BS_STRIDE)

template <int KHALF, bool CVT>
__global__ void __launch_bounds__(256, 2)
sage_tf32(const float* __restrict__ A0, const float* __restrict__ A1,
          const float* __restrict__ W, const float* __restrict__ bias,
          float* __restrict__ C) {
    extern __shared__ float smem[];
    float* As = smem;
    float* Bs = smem + 2 * AS_BUF;

    const int tid = threadIdx.x;
    const int lane = tid & 31;
    const int wid = tid >> 5;
    const int wm = wid & 3;
    const int wn = wid >> 2;
    const int rowBase = blockIdx.x * 128;
    const int colBase = blockIdx.y * 128;
    const int NT = (2 * KHALF) / 32;

    float acc[2][8][4];
#pragma unroll
    for (int i = 0; i < 2; i++)
#pragma unroll
        for (int j = 0; j < 8; j++)
#pragma unroll
            for (int k = 0; k < 4; k++) acc[i][j][k] = 0.0f;

    auto issue = [&](int buf, int k0) {
        float* Asb = As + buf * AS_BUF;
        float* Bsb = Bs + buf * BS_BUF;
        const float* Abase = (k0 < KHALF) ? A0 : A1;
        int kb = (k0 < KHALF) ? k0 : (k0 - KHALF);
#pragma unroll
        for (int i = 0; i < 4; i++) {
            int idx = tid + 256 * i;
            int r = idx >> 3, kc = idx & 7;
            int row = rowBase + r;
            const float* src = Abase + (size_t)row * KHALF + kb + kc * 4;
            uint32_t dst = (uint32_t)__cvta_generic_to_shared(Asb + r * AS_STRIDE + kc * 4);
            int sz = (row < N_NODES) ? 16 : 0;
            asm volatile("cp.async.ca.shared.global [%0], [%1], 16, %2;"
                         :: "r"(dst), "l"(src), "r"(sz));
        }
#pragma unroll
        for (int i = 0; i < 4; i++) {
            int idx = tid + 256 * i;
            int k = idx >> 5, c4 = idx & 31;
            const float* src = W + (size_t)(k0 + k) * HID + colBase + c4 * 4;
            uint32_t dst = (uint32_t)__cvta_generic_to_shared(Bsb + k * BS_STRIDE + c4 * 4);
            asm volatile("cp.async.ca.shared.global [%0], [%1], 16;"
                         :: "r"(dst), "l"(src));
        }
        asm volatile("cp.async.commit_group;");
    };

    issue(0, 0);
    for (int t = 0; t < NT; t++) {
        if (t + 1 < NT) {
            issue((t + 1) & 1, (t + 1) * 32);
            asm volatile("cp.async.wait_group 1;");
        } else {
            asm volatile("cp.async.wait_group 0;");
        }
        __syncthreads();
        const float* Asb = As + (t & 1) * AS_BUF;
        const float* Bsb = Bs + (t & 1) * BS_BUF;
#pragma unroll
        for (int k8 = 0; k8 < 4; k8++) {
            int kb = k8 * 8;
            uint32_t a[2][4];
#pragma unroll
            for (int mt = 0; mt < 2; mt++) {
                int m = wm * 32 + mt * 16 + (lane >> 2);
                int k = kb + (lane & 3);
                a[mt][0] = __float_as_uint(Asb[m * AS_STRIDE + k]);
                a[mt][1] = __float_as_uint(Asb[(m + 8) * AS_STRIDE + k]);
                a[mt][2] = __float_as_uint(Asb[m * AS_STRIDE + k + 4]);
                a[mt][3] = __float_as_uint(Asb[(m + 8) * AS_STRIDE + k + 4]);
            }
#pragma unroll
            for (int nt = 0; nt < 8; nt++) {
                int n = wn * 64 + nt * 8 + (lane >> 2);
                int k = kb + (lane & 3);
                uint32_t b0 = __float_as_uint(Bsb[k * BS_STRIDE + n]);
                uint32_t b1 = __float_as_uint(Bsb[(k + 4) * BS_STRIDE + n]);
                mma_tf32(acc[0][nt], a[0], b0, b1);
                mma_tf32(acc[1][nt], a[1], b0, b1);
            }
        }
        __syncthreads();
    }

#pragma unroll
    for (int mt = 0; mt < 2; mt++) {
        int r0 = rowBase + wm * 32 + mt * 16 + (lane >> 2);
#pragma unroll
        for (int nt = 0; nt < 8; nt++) {
            int c = colBase + wn * 64 + nt * 8 + (lane & 3) * 2;
            float bv0 = __ldg(bias + c);
            float bv1 = __ldg(bias + c + 1);
            float v0 = fmaxf(acc[mt][nt][0] + bv0, 0.0f);
            float v1 = fmaxf(acc[mt][nt][1] + bv1, 0.0f);
            float v2 = fmaxf(acc[mt][nt][2] + bv0, 0.0f);
            float v3 = fmaxf(acc[mt][nt][3] + bv1, 0.0f);
            if (CVT) {
                v0 = to_tf32(v0); v1 = to_tf32(v1);
                v2 = to_tf32(v2); v3 = to_tf32(v3);
            }
            if (r0 < N_NODES)
                *reinterpret_cast<float2*>(C + (size_t)r0 * HID + c) = make_float2(v0, v1);
            if (r0 + 8 < N_NODES)
                *reinterpret_cast<float2*>(C + (size_t)(r0 + 8) * HID + c) = make_float2(v2, v3);
        }
    }
}

// ---------------- classifier ----------------
__global__ void classifier_k(const float* __restrict__ wc,
                             const float* __restrict__ bc,
                             float* __restrict__ out) {
    __shared__ float w[HID * N_CLASSES];
    __shared__ float hrow[8][HID];
    for (int i = threadIdx.x; i < HID * N_CLASSES; i += blockDim.x)
        w[i] = wc[i];
    __syncthreads();

    int warp = threadIdx.x >> 5;
    int lane = threadIdx.x & 31;
    int row = blockIdx.x * 8 + warp;
    if (row >= N_NODES) return;

    const float* h = g_h2 + (size_t)row * HID;
    for (int k = lane; k < HID; k += 32) hrow[warp][k] = h[k];
    __syncwarp();

    int c = lane & 15;
    int p = lane >> 4;
    float acc = 0.0f;
    int kbeg = p * (HID / 2);
#pragma unroll 8
    for (int k = kbeg; k < kbeg + HID / 2; k++)
        acc += hrow[warp][k] * w[k * N_CLASSES + c];
    acc += __shfl_xor_sync(0xffffffffu, acc, 16);
    if (lane < 16) out[(size_t)row * N_CLASSES + lane] = acc + bc[lane];
}

// ---------------- launch ----------------
extern "C" void kernel_launch(void* const* d_in, const int* in_sizes, int n_in,
                              void* d_out, int out_size) {
    const float* x    = (const float*)d_in[0];
    const int*   ei   = (const int*)d_in[1];
    const float* w1_l = (const float*)d_in[2];
    const float* b1_l = (const float*)d_in[3];
    const float* w1_r = (const float*)d_in[4];
    const float* w2_l = (const float*)d_in[5];
    const float* b2_l = (const float*)d_in[6];
    const float* w2_r = (const float*)d_in[7];
    const float* wc   = (const float*)d_in[8];
    const float* bc   = (const float*)d_in[9];
    float* out = (float*)d_out;

    // resolve REAL device addresses (GB300 ATS pitfall: never pass symbols as args)
    void *p_agg, *p_h1, *p_h2, *p_xt, *p_w1t, *p_w2t;
    cudaGetSymbolAddress(&p_agg, g_agg);
    cudaGetSymbolAddress(&p_h1,  g_h1);
    cudaGetSymbolAddress(&p_h2,  g_h2);
    cudaGetSymbolAddress(&p_xt,  g_xt);
    cudaGetSymbolAddress(&p_w1t, g_w1t);
    cudaGetSymbolAddress(&p_w2t, g_w2t);

    const int SMEM = (2 * AS_BUF + 2 * BS_BUF) * 4;
    cudaFuncSetAttribute(sage_tf32<IN_DIM, true>,
                         cudaFuncAttributeMaxDynamicSharedMemorySize, SMEM);
    cudaFuncSetAttribute(sage_tf32<HID, false>,
                         cudaFuncAttributeMaxDynamicSharedMemorySize, SMEM);

    // ---- CSR build ----
    zero_cnt<<<(N_NODES + 255) / 256, 256>>>();
    hist_kernel<<<(N_EDGES + 255) / 256, 256>>>(ei);
    block_reduce_k<<<N_SBLOCKS, SCAN_BLOCK>>>();
    scan_blocksums_k<<<1, 256>>>();
    block_scan_k<<<N_SBLOCKS, SCAN_BLOCK>>>();
    fill_kernel<<<(N_EDGES + 255) / 256, 256>>>(ei);

    // ---- tf32 input conversions ----
    cvt_concat<<<(2 * IN_DIM * HID + 255) / 256, 256>>>((float*)p_w1t, w1_l, w1_r, IN_DIM * HID);
    cvt_concat<<<(2 * HID * HID + 255) / 256, 256>>>((float*)p_w2t, w2_l, w2_r, HID * HID);
    cvt_copy<<<(N_NODES * IN_DIM + 255) / 256, 256>>>((float*)p_xt, x, N_NODES * IN_DIM);

    // ---- layer 1 ----
    gather_mean_128<<<(N_NODES * 32 + 255) / 256, 256>>>(x);
    {
        dim3 grid((N_NODES + 127) / 128, HID / 128);
        sage_tf32<IN_DIM, true><<<grid, 256, SMEM>>>(
            (const float*)p_agg, (const float*)p_xt, (const float*)p_w1t, b1_l, (float*)p_h1);
    }

    // ---- layer 2 ----
    gather_mean_256<<<(N_NODES * 32 + 255) / 256, 256>>>();
    {
        dim3 grid((N_NODES + 127) / 128, HID / 128);
        sage_tf32<HID, false><<<grid, 256, SMEM>>>(
            (const float*)p_agg, (const float*)p_h1, (const float*)p_w2t, b2_l, (float*)p_h2);
    }

    // ---- classifier ----
    classifier_k<<<(N_NODES + 7) / 8, 256>>>(wc, bc, out);
}